// round 10
// baseline (speedup 1.0000x reference)
#include <cuda_runtime.h>
#include <cstdint>
#include <cstddef>

#define BD 128     // batch
#define TD 256     // seq len
#define HD 512     // hidden
#define G3 1536    // 3*H
#define LD 3       // layers
#define MD (BD*TD) // 32768 rows for input GEMM

// ---------------- scratch (static device allocations; no cudaMalloc) -------
__device__ float g_XP[(size_t)MD * G3];          // input projections
__device__ float g_X1[(size_t)MD * HD];          // layer0 seq out
__device__ float g_X2[(size_t)MD * HD];          // layer1 seq out
__device__ float g_WuT[(size_t)LD * G3 * HD];    // transposed recurrent weights
__device__ float g_hT[2 * HD * BD];              // ping-pong hidden state, [j][b]
__device__ unsigned int g_bar[LD];               // per-layer grid barrier counters

// ---------------- helpers --------------------------------------------------
__device__ __forceinline__ void cp16(float* dst, const float* src) {
    unsigned s = (unsigned)__cvta_generic_to_shared(dst);
    asm volatile("cp.async.cg.shared.global [%0], [%1], 16;\n" :: "r"(s), "l"(src) : "memory");
}
__device__ __forceinline__ float fast_sigmoid(float x) {
    return __fdividef(1.0f, 1.0f + __expf(-x));
}
__device__ __forceinline__ float fast_tanh(float x) {
    x = fminf(15.0f, fmaxf(-15.0f, x));
    float t = __expf(2.0f * x);
    return __fdividef(t - 1.0f, t + 1.0f);
}

// ---------------- transpose rec_kernels: [L][512][1536] -> [L][1536][512] --
__global__ void k_trans(const float* __restrict__ in, float* __restrict__ out) {
    __shared__ float s[32][33];
    const int l  = blockIdx.z;
    const int n0 = blockIdx.x * 32;
    const int k0 = blockIdx.y * 32;
    const float* inl  = in  + (size_t)l * HD * G3;
    float*       outl = out + (size_t)l * G3 * HD;
    for (int r = threadIdx.y; r < 32; r += 8)
        s[r][threadIdx.x] = inl[(size_t)(k0 + r) * G3 + n0 + threadIdx.x];
    __syncthreads();
    for (int r = threadIdx.y; r < 32; r += 8)
        outl[(size_t)(n0 + r) * HD + k0 + threadIdx.x] = s[threadIdx.x][r];
}

// separate tiny kernels so ncu -s 5 lands on gemm(layer1):
// launches: 0 trans, 1 zeroH, 2 zeroBar, 3 gemm0, 4 scan0, 5 gemm1 <- profiled
__global__ void k_zeroH(float* p, int n) {
    int i = blockIdx.x * blockDim.x + threadIdx.x;
    if (i < n) p[i] = 0.0f;
}
__global__ void k_zeroBar() {
    if (threadIdx.x < LD) g_bar[threadIdx.x] = 0u;
}

// final state: d_out tail [b][j] from hT [j][b]
__global__ void k_final(const float* __restrict__ hT0, float* __restrict__ out) {
    int idx = blockIdx.x * blockDim.x + threadIdx.x;  // 65536
    int b = idx >> 9, j = idx & 511;
    out[idx] = hT0[(size_t)j * BD + b];
}

// ---------------- input GEMM: C[M,1536] = A[M,512] @ Bw[512,1536] + bias ---
// 128x128 tile, kTile 16, 2-stage smem, ONE syncthreads per tile,
// 2 CTAs/SM (launch_bounds(256,2)).
__global__ __launch_bounds__(256, 2)
void k_gemm(const float* __restrict__ A, const float* __restrict__ Bw,
            const float* __restrict__ bias, float* __restrict__ C) {
    __shared__ float As[2][16][132];   // [stage][k][m] padded
    __shared__ float Bs[2][16][132];   // [stage][k][n] padded
    const int tid = threadIdx.x;
    const int n0 = blockIdx.x * 128;
    const int m0 = blockIdx.y * 128;
    const int tx = tid & 15;
    const int ty = tid >> 4;
    const int arow = tid >> 2;      // 0..63
    const int af   = tid & 3;       // k-float4 slot
    const int brow = tid >> 4;      // 0..15
    const int bf   = tid & 15;

    float acc[8][8];
#pragma unroll
    for (int i = 0; i < 8; i++)
#pragma unroll
        for (int jj = 0; jj < 8; jj++) acc[i][jj] = 0.0f;

    float4 av0, av1, bv0, bv1;
    // prologue: load k-tile 0 into regs
    av0 = *(const float4*)(A + (size_t)(m0 + arow) * HD + af * 4);
    av1 = *(const float4*)(A + (size_t)(m0 + arow + 64) * HD + af * 4);
    bv0 = *(const float4*)(Bw + (size_t)brow * G3 + n0 + bf * 4);
    bv1 = *(const float4*)(Bw + (size_t)brow * G3 + n0 + 64 + bf * 4);

    for (int kt = 0; kt < 32; kt++) {
        const int st = kt & 1;
        // STS current tile into stage st
        As[st][af * 4 + 0][arow]      = av0.x;
        As[st][af * 4 + 1][arow]      = av0.y;
        As[st][af * 4 + 2][arow]      = av0.z;
        As[st][af * 4 + 3][arow]      = av0.w;
        As[st][af * 4 + 0][arow + 64] = av1.x;
        As[st][af * 4 + 1][arow + 64] = av1.y;
        As[st][af * 4 + 2][arow + 64] = av1.z;
        As[st][af * 4 + 3][arow + 64] = av1.w;
        *(float4*)&Bs[st][brow][bf * 4]      = bv0;
        *(float4*)&Bs[st][brow][64 + bf * 4] = bv1;
        __syncthreads();   // single barrier per tile (2-stage proof in header)

        // prefetch next tile into regs while computing
        if (kt < 31) {
            const int k0 = (kt + 1) * 16;
            av0 = *(const float4*)(A + (size_t)(m0 + arow) * HD + k0 + af * 4);
            av1 = *(const float4*)(A + (size_t)(m0 + arow + 64) * HD + k0 + af * 4);
            bv0 = *(const float4*)(Bw + (size_t)(k0 + brow) * G3 + n0 + bf * 4);
            bv1 = *(const float4*)(Bw + (size_t)(k0 + brow) * G3 + n0 + 64 + bf * 4);
        }

#pragma unroll
        for (int k = 0; k < 16; k++) {
            float a0[8], b0r[8];
            *(float4*)&a0[0]  = *(const float4*)&As[st][k][ty * 4];
            *(float4*)&a0[4]  = *(const float4*)&As[st][k][ty * 4 + 64];
            *(float4*)&b0r[0] = *(const float4*)&Bs[st][k][tx * 4];
            *(float4*)&b0r[4] = *(const float4*)&Bs[st][k][tx * 4 + 64];
#pragma unroll
            for (int i = 0; i < 8; i++)
#pragma unroll
                for (int jj = 0; jj < 8; jj++) acc[i][jj] += a0[i] * b0r[jj];
        }
    }

    float bv[8];
#pragma unroll
    for (int jj = 0; jj < 4; jj++) {
        bv[jj]     = bias[n0 + tx * 4 + jj];
        bv[4 + jj] = bias[n0 + 64 + tx * 4 + jj];
    }
#pragma unroll
    for (int i = 0; i < 8; i++) {
        int m = m0 + ty * 4 + (i & 3) + (i >> 2) * 64;
        float* crow = C + (size_t)m * G3 + n0;
        float4 o0, o1;
        o0.x = acc[i][0] + bv[0]; o0.y = acc[i][1] + bv[1];
        o0.z = acc[i][2] + bv[2]; o0.w = acc[i][3] + bv[3];
        o1.x = acc[i][4] + bv[4]; o1.y = acc[i][5] + bv[5];
        o1.z = acc[i][6] + bv[6]; o1.w = acc[i][7] + bv[7];
        *(float4*)(crow + tx * 4)      = o0;
        *(float4*)(crow + 64 + tx * 4) = o1;
    }
}

// ---------------- persistent recurrent scan --------------------------------
// grid 128 = 2 b-tiles x 64 j-blocks (8 j each). 128 threads.
// Thread: 4 b's x 1 j x 3 gates. One grid barrier per step.
#define SCAN_THREADS 128
#define WS_STRIDE 516
#define SCAN_SMEM ((24 * WS_STRIDE + 512 * 64) * 4)

__global__ __launch_bounds__(SCAN_THREADS, 1)
void k_scan(const float* __restrict__ XP, const float* __restrict__ WuT,
            const float* __restrict__ br, float* __restrict__ seq,
            float* __restrict__ hT0, float* __restrict__ hT1,
            unsigned int* __restrict__ bar) {
    extern __shared__ float sm[];
    float* Ws = sm;                       // [24][516]
    float* hs = sm + 24 * WS_STRIDE;      // [512][64]  (k-major, b fast)
    const int tid  = threadIdx.x;
    const int bt   = blockIdx.x & 1;
    const int jblk = blockIdx.x >> 1;
    const int j0   = jblk * 8;
    const int tb   = tid & 15;
    const int tj   = tid >> 4;
    const int bloc = tb * 4;
    const int b0   = bt * 64 + bloc;
    const int j    = j0 + tj;

    for (int r = 0; r < 24; r++) {
        const int g = r >> 3, jj = r & 7;
        const float4* src = (const float4*)(WuT + (size_t)(g * HD + j0 + jj) * HD);
        ((float4*)(Ws + r * WS_STRIDE))[tid] = src[tid];
    }
    __syncthreads();

    const float brz = br[j], brr = br[HD + j], brh = br[2 * HD + j];
    const float* w0 = Ws + (0 * 8 + tj) * WS_STRIDE;
    const float* w1 = Ws + (1 * 8 + tj) * WS_STRIDE;
    const float* w2 = Ws + (2 * 8 + tj) * WS_STRIDE;

    unsigned int bar_target = 0;
    for (int t = 0; t < TD; t++) {
        const float* hcur = (t & 1) ? hT1 : hT0;
        float*       hnxt = (t & 1) ? hT0 : hT1;

#pragma unroll
        for (int c = 0; c < 4; c++) {
            const float* src = hcur + (size_t)(c * 128) * BD + bt * 64;
#pragma unroll
            for (int i = 0; i < 16; i++) {
                int idx = tid + i * 128;
                int k = idx >> 4, f = idx & 15;
                cp16(hs + (size_t)(c * 128 + k) * 64 + f * 4,
                     src + (size_t)k * BD + f * 4);
            }
            asm volatile("cp.async.commit_group;\n" ::: "memory");
        }

        float acc[4][3];
#pragma unroll
        for (int i = 0; i < 4; i++) { acc[i][0] = 0.f; acc[i][1] = 0.f; acc[i][2] = 0.f; }

#pragma unroll
        for (int c = 0; c < 4; c++) {
            if (c == 0)      asm volatile("cp.async.wait_group 3;\n" ::: "memory");
            else if (c == 1) asm volatile("cp.async.wait_group 2;\n" ::: "memory");
            else if (c == 2) asm volatile("cp.async.wait_group 1;\n" ::: "memory");
            else             asm volatile("cp.async.wait_group 0;\n" ::: "memory");
            __syncthreads();
            const float* hc = hs + (size_t)c * 128 * 64 + bloc;
            const float* wz = w0 + c * 128;
            const float* wr = w1 + c * 128;
            const float* wh = w2 + c * 128;
#pragma unroll 8
            for (int k = 0; k < 128; k++) {
                float4 hv = *(const float4*)(hc + (size_t)k * 64);
                float a = wz[k], b = wr[k], cc = wh[k];
                acc[0][0] += hv.x * a;  acc[1][0] += hv.y * a;
                acc[2][0] += hv.z * a;  acc[3][0] += hv.w * a;
                acc[0][1] += hv.x * b;  acc[1][1] += hv.y * b;
                acc[2][1] += hv.z * b;  acc[3][1] += hv.w * b;
                acc[0][2] += hv.x * cc; acc[1][2] += hv.y * cc;
                acc[2][2] += hv.z * cc; acc[3][2] += hv.w * cc;
            }
        }

        // gate math + state update (fast transcendentals)
        float hn4[4];
#pragma unroll
        for (int i = 0; i < 4; i++) {
            const int b = b0 + i;
            const float* xprow = XP + ((size_t)b * TD + t) * G3;
            float xz = xprow[j], xr = xprow[HD + j], xh = xprow[2 * HD + j];
            float z  = fast_sigmoid(xz + acc[i][0] + brz);
            float r  = fast_sigmoid(xr + acc[i][1] + brr);
            float hh = fast_tanh(xh + r * (acc[i][2] + brh));
            float ho = hs[(size_t)j * 64 + bloc + i];
            float hn = z * ho + (1.0f - z) * hh;
            hn4[i] = hn;
            seq[((size_t)b * TD + t) * HD + j] = hn;
        }
        *(float4*)(hnxt + (size_t)j * BD + b0) = *(float4*)hn4;

        // grid barrier
        bar_target += gridDim.x;
        __syncthreads();
        if (tid == 0) {
            __threadfence();
            atomicAdd(bar, 1u);
            while (atomicAdd(bar, 0u) < bar_target) { }
            __threadfence();
        }
        __syncthreads();
    }
}

// ---------------- launch ---------------------------------------------------
extern "C" void kernel_launch(void* const* d_in, const int* in_sizes, int n_in,
                              void* d_out, int out_size) {
    const float* x      = (const float*)d_in[0];  // [128,256,512]
    const float* kern   = (const float*)d_in[1];  // [3,512,1536]
    const float* rkern  = (const float*)d_in[2];  // [3,512,1536]
    const float* biases = (const float*)d_in[3];  // [3,2,1536]
    float* out = (float*)d_out;

    cudaFuncSetAttribute(k_scan, cudaFuncAttributeMaxDynamicSharedMemorySize, SCAN_SMEM);

    float *XP, *X1, *X2, *WuT, *hT;
    unsigned int* bar;
    cudaGetSymbolAddress((void**)&XP,  g_XP);
    cudaGetSymbolAddress((void**)&X1,  g_X1);
    cudaGetSymbolAddress((void**)&X2,  g_X2);
    cudaGetSymbolAddress((void**)&WuT, g_WuT);
    cudaGetSymbolAddress((void**)&hT,  g_hT);
    cudaGetSymbolAddress((void**)&bar, g_bar);
    float* hT0 = hT;
    float* hT1 = hT + HD * BD;

    // launch order matters for ncu -s 5 -c 1: index 5 == gemm(layer1)
    k_trans<<<dim3(G3 / 32, HD / 32, LD), dim3(32, 8)>>>(rkern, WuT);   // 0
    k_zeroH<<<(HD * BD + 255) / 256, 256>>>(hT0, HD * BD);              // 1
    k_zeroBar<<<1, 32>>>();                                             // 2

    const float* cur = x;
    float* outs[3] = {X1, X2, out};
    for (int l = 0; l < LD; l++) {
        const float* Wk = kern + (size_t)l * HD * G3;
        const float* b0 = biases + (size_t)l * 2 * G3;
        k_gemm<<<dim3(G3 / 128, MD / 128), 256>>>(cur, Wk, b0, XP);     // 3,5,7
        k_scan<<<128, SCAN_THREADS, SCAN_SMEM>>>(
            XP, WuT + (size_t)l * G3 * HD, b0 + G3, outs[l], hT0, hT1, bar + l);
        cur = outs[l];
    }
    k_final<<<(HD * BD + 511) / 512, 512>>>(hT0, out + (size_t)MD * HD);
}

// round 15
// speedup vs baseline: 1.4695x; 1.4695x over previous
#include <cuda_runtime.h>
#include <cstdint>
#include <cstddef>

#define BD 128     // batch
#define TD 256     // seq len
#define HD 512     // hidden
#define G3 1536    // 3*H
#define LD 3       // layers
#define MD (BD*TD) // 32768 rows for input GEMM

typedef unsigned long long ull;

// ---------------- scratch (static device allocations; no cudaMalloc) -------
__device__ float g_XP[(size_t)MD * G3];          // input projections
__device__ float g_X1[(size_t)MD * HD];          // layer0 seq out
__device__ float g_X2[(size_t)MD * HD];          // layer1 seq out
__device__ float g_WuT[(size_t)LD * G3 * HD];    // transposed recurrent weights
__device__ float g_hT[2 * HD * BD];              // ping-pong hidden state, [j][b]
__device__ unsigned int g_bar[LD];               // per-layer grid barrier counters

// ---------------- helpers --------------------------------------------------
__device__ __forceinline__ void cp16(float* dst, const float* src) {
    unsigned s = (unsigned)__cvta_generic_to_shared(dst);
    asm volatile("cp.async.cg.shared.global [%0], [%1], 16;\n" :: "r"(s), "l"(src) : "memory");
}
__device__ __forceinline__ float fast_sigmoid(float x) {
    return __fdividef(1.0f, 1.0f + __expf(-x));
}
__device__ __forceinline__ float fast_tanh(float x) {
    x = fminf(15.0f, fmaxf(-15.0f, x));
    float t = __expf(2.0f * x);
    return __fdividef(t - 1.0f, t + 1.0f);
}
// packed fp32x2 (Blackwell FFMA2 path)
__device__ __forceinline__ ull pack2(float lo, float hi) {
    ull r; asm("mov.b64 %0, {%1, %2};" : "=l"(r) : "f"(lo), "f"(hi)); return r;
}
__device__ __forceinline__ float2 unpack2(ull v) {
    float2 f; asm("mov.b64 {%0, %1}, %2;" : "=f"(f.x), "=f"(f.y) : "l"(v)); return f;
}
__device__ __forceinline__ void ffma2(ull& d, ull a, ull b) {
    asm("fma.rn.f32x2 %0, %1, %2, %0;" : "+l"(d) : "l"(a), "l"(b));
}

// ---------------- transpose rec_kernels: [L][512][1536] -> [L][1536][512] --
__global__ void k_trans(const float* __restrict__ in, float* __restrict__ out) {
    __shared__ float s[32][33];
    const int l  = blockIdx.z;
    const int n0 = blockIdx.x * 32;
    const int k0 = blockIdx.y * 32;
    const float* inl  = in  + (size_t)l * HD * G3;
    float*       outl = out + (size_t)l * G3 * HD;
    for (int r = threadIdx.y; r < 32; r += 8)
        s[r][threadIdx.x] = inl[(size_t)(k0 + r) * G3 + n0 + threadIdx.x];
    __syncthreads();
    for (int r = threadIdx.y; r < 32; r += 8)
        outl[(size_t)(n0 + r) * HD + k0 + threadIdx.x] = s[threadIdx.x][r];
}

// launches: 0 trans, 1 zeroH, 2 zeroBar, 3 gemm0, 4 scan0, 5 gemm1 <- ncu -s 5
__global__ void k_zeroH(float* p, int n) {
    int i = blockIdx.x * blockDim.x + threadIdx.x;
    if (i < n) p[i] = 0.0f;
}
__global__ void k_zeroBar() {
    if (threadIdx.x < LD) g_bar[threadIdx.x] = 0u;
}

__global__ void k_final(const float* __restrict__ hT0, float* __restrict__ out) {
    int idx = blockIdx.x * blockDim.x + threadIdx.x;  // 65536
    int b = idx >> 9, j = idx & 511;
    out[idx] = hT0[(size_t)j * BD + b];
}

// ---------------- input GEMM (f32x2): C = A[M,512] @ Bw[512,1536] + bias ---
// 128x128 tile, kTile 16, 2-stage smem, 1 sync/tile, A stored as dup-pairs.
#define AR 268                            // As2 k-row stride in floats (128 pairs + pad)
#define GEMM_SMEM ((2 * 16 * AR + 2 * 16 * 132) * 4)

__global__ __launch_bounds__(256, 1)
void k_gemm(const float* __restrict__ A, const float* __restrict__ Bw,
            const float* __restrict__ bias, float* __restrict__ C) {
    extern __shared__ float smg[];
    float* As2 = smg;                     // [2][16][AR]: (a,a) pairs, idx = pair m
    float* Bs  = smg + 2 * 16 * AR;       // [2][16][132]
    const int tid = threadIdx.x;
    const int n0 = blockIdx.x * 128;
    const int m0 = blockIdx.y * 128;
    const int tx = tid & 15;
    const int ty = tid >> 4;
    const int arow = tid >> 2;            // m 0..63
    const int af   = tid & 3;             // k-quad
    const int brow = tid >> 4;            // k 0..15
    const int bf   = tid & 15;

    ull acc2[8][4];
#pragma unroll
    for (int i = 0; i < 8; i++)
#pragma unroll
        for (int p = 0; p < 4; p++) acc2[i][p] = 0ull;

    float4 av0, av1, bv0, bv1;
    av0 = *(const float4*)(A + (size_t)(m0 + arow) * HD + af * 4);
    av1 = *(const float4*)(A + (size_t)(m0 + arow + 64) * HD + af * 4);
    bv0 = *(const float4*)(Bw + (size_t)brow * G3 + n0 + bf * 4);
    bv1 = *(const float4*)(Bw + (size_t)brow * G3 + n0 + 64 + bf * 4);

    for (int kt = 0; kt < 32; kt++) {
        const int st = kt & 1;
        float* as = As2 + st * 16 * AR;
        float* bs = Bs  + st * 16 * 132;
        // STS: A duplicated (a,a), B plain
        {
            float va[4] = {av0.x, av0.y, av0.z, av0.w};
            float vb[4] = {av1.x, av1.y, av1.z, av1.w};
#pragma unroll
            for (int j = 0; j < 4; j++) {
                const int k = af * 4 + j;
                *(float2*)(as + k * AR + arow * 2)        = make_float2(va[j], va[j]);
                *(float2*)(as + k * AR + (arow + 64) * 2) = make_float2(vb[j], vb[j]);
            }
            *(float4*)(bs + brow * 132 + bf * 4)      = bv0;
            *(float4*)(bs + brow * 132 + 64 + bf * 4) = bv1;
        }
        __syncthreads();   // single barrier per tile (2-stage: safe)

        if (kt < 31) {
            const int k0 = (kt + 1) * 16;
            av0 = *(const float4*)(A + (size_t)(m0 + arow) * HD + k0 + af * 4);
            av1 = *(const float4*)(A + (size_t)(m0 + arow + 64) * HD + k0 + af * 4);
            bv0 = *(const float4*)(Bw + (size_t)(k0 + brow) * G3 + n0 + bf * 4);
            bv1 = *(const float4*)(Bw + (size_t)(k0 + brow) * G3 + n0 + 64 + bf * 4);
        }

#pragma unroll
        for (int k = 0; k < 16; k++) {
            const float* arp = as + k * AR + ty * 8;
            const float* brp = bs + k * 132 + tx * 4;
            ulonglong2 qa0 = *(const ulonglong2*)(arp);         // dup m0,m1
            ulonglong2 qa1 = *(const ulonglong2*)(arp + 4);     // dup m2,m3
            ulonglong2 qa2 = *(const ulonglong2*)(arp + 128);   // dup m4,m5 (+64 rows)
            ulonglong2 qa3 = *(const ulonglong2*)(arp + 132);   // dup m6,m7
            ulonglong2 qb0 = *(const ulonglong2*)(brp);         // (n0,n1),(n2,n3)
            ulonglong2 qb1 = *(const ulonglong2*)(brp + 64);    // (+64 cols)
            ull ad[8] = {qa0.x, qa0.y, qa1.x, qa1.y, qa2.x, qa2.y, qa3.x, qa3.y};
            ull bp[4] = {qb0.x, qb0.y, qb1.x, qb1.y};
#pragma unroll
            for (int i = 0; i < 8; i++)
#pragma unroll
                for (int p = 0; p < 4; p++) ffma2(acc2[i][p], ad[i], bp[p]);
        }
    }

    float bvv[8];
#pragma unroll
    for (int jj = 0; jj < 4; jj++) {
        bvv[jj]     = bias[n0 + tx * 4 + jj];
        bvv[4 + jj] = bias[n0 + 64 + tx * 4 + jj];
    }
#pragma unroll
    for (int i = 0; i < 8; i++) {
        const int m = m0 + ty * 4 + (i & 3) + (i >> 2) * 64;
        float* crow = C + (size_t)m * G3 + n0;
        float2 c0 = unpack2(acc2[i][0]);
        float2 c1 = unpack2(acc2[i][1]);
        float2 c2 = unpack2(acc2[i][2]);
        float2 c3 = unpack2(acc2[i][3]);
        float4 o0 = {c0.x + bvv[0], c0.y + bvv[1], c1.x + bvv[2], c1.y + bvv[3]};
        float4 o1 = {c2.x + bvv[4], c2.y + bvv[5], c3.x + bvv[6], c3.y + bvv[7]};
        *(float4*)(crow + tx * 4)      = o0;
        *(float4*)(crow + 64 + tx * 4) = o1;
    }
}

// ---------------- persistent recurrent scan (f32x2) -------------------------
// grid 128 = 2 b-tiles x 64 j-blocks (8 j each). 128 threads.
// Thread: 2 j (pair, f32x2 lanes) x 2 b x 3 gates = 6 packed accumulators.
#define SCAN_THREADS 128
#define WS2_FLOATS (3 * 512 * 8)              // [gate][k][8 j] interleaved
#define SCAN_SMEM ((WS2_FLOATS + 512 * 64) * 4)

__global__ __launch_bounds__(SCAN_THREADS, 1)
void k_scan(const float* __restrict__ XP, const float* __restrict__ WuT,
            const float* __restrict__ br, float* __restrict__ seq,
            float* __restrict__ hT0, float* __restrict__ hT1,
            unsigned int* __restrict__ bar) {
    extern __shared__ float sm[];
    float* Ws2 = sm;                      // [3][512][8] floats
    float* hs  = sm + WS2_FLOATS;         // [512][64]  (k-major, b fast)
    const int tid  = threadIdx.x;
    const int bt   = blockIdx.x & 1;
    const int jblk = blockIdx.x >> 1;
    const int j0   = jblk * 8;            // CTA's global j base
    const int jp   = tid & 3;             // j-pair 0..3
    const int bp   = tid >> 2;            // b-pair 0..31
    const int bloc = bp * 2;              // local b base (0..62)
    const int b0g  = bt * 64 + bloc;      // global b base
    const int jg0  = j0 + jp * 2;         // global j base (even)

    // stage Wu^T -> Ws2[g][k][jj]: pair-adjacent j for LDS.64 f32x2 operands
    for (int r = 0; r < 24; r++) {
        const int g = r >> 3, jj = r & 7;
        float4 v = ((const float4*)(WuT + (size_t)(g * HD + j0 + jj) * HD))[tid];
        float* dst = Ws2 + g * 4096 + (tid * 4) * 8 + jj;
        dst[0]  = v.x; dst[8]  = v.y; dst[16] = v.z; dst[24] = v.w;
    }
    __syncthreads();

    const float2 brz2 = *(const float2*)(br + jg0);
    const float2 brr2 = *(const float2*)(br + HD + jg0);
    const float2 brh2 = *(const float2*)(br + 2 * HD + jg0);
    const float* wzb = Ws2 + 0 * 4096 + jp * 2;
    const float* wrb = Ws2 + 1 * 4096 + jp * 2;
    const float* whb = Ws2 + 2 * 4096 + jp * 2;

    unsigned int bar_target = 0;
    for (int t = 0; t < TD; t++) {
        const float* hcur = (t & 1) ? hT1 : hT0;
        float*       hnxt = (t & 1) ? hT0 : hT1;

        // issue 4 k-chunks of h into smem via cp.async
#pragma unroll
        for (int c = 0; c < 4; c++) {
            const float* src = hcur + (size_t)(c * 128) * BD + bt * 64;
#pragma unroll
            for (int i = 0; i < 16; i++) {
                int idx = tid + i * 128;
                int k = idx >> 4, f = idx & 15;
                cp16(hs + (size_t)(c * 128 + k) * 64 + f * 4,
                     src + (size_t)k * BD + f * 4);
            }
            asm volatile("cp.async.commit_group;\n" ::: "memory");
        }

        ull az[2] = {0ull, 0ull}, ar2[2] = {0ull, 0ull}, ah[2] = {0ull, 0ull};

#pragma unroll
        for (int c = 0; c < 4; c++) {
            if (c == 0)      asm volatile("cp.async.wait_group 3;\n" ::: "memory");
            else if (c == 1) asm volatile("cp.async.wait_group 2;\n" ::: "memory");
            else if (c == 2) asm volatile("cp.async.wait_group 1;\n" ::: "memory");
            else             asm volatile("cp.async.wait_group 0;\n" ::: "memory");
            __syncthreads();
            const int kg0 = c * 128;
            const float* hc = hs + (size_t)kg0 * 64 + bloc;
            const float* wz = wzb + kg0 * 8;
            const float* wr = wrb + kg0 * 8;
            const float* wh = whb + kg0 * 8;
#pragma unroll 8
            for (int k = 0; k < 128; k++) {
                const ull wzp = *(const ull*)(wz + k * 8);       // (w[j0], w[j1])
                const ull wrp = *(const ull*)(wr + k * 8);
                const ull whp = *(const ull*)(wh + k * 8);
                const float2 hp = *(const float2*)(hc + k * 64); // h[b0], h[b1]
                const ull h0 = pack2(hp.x, hp.x);
                const ull h1 = pack2(hp.y, hp.y);
                ffma2(az[0], wzp, h0);  ffma2(az[1], wzp, h1);
                ffma2(ar2[0], wrp, h0); ffma2(ar2[1], wrp, h1);
                ffma2(ah[0], whp, h0);  ffma2(ah[1], whp, h1);
            }
        }

        // gate math + state update: 2 b x 2 j per thread
        float2 hn[2];
#pragma unroll
        for (int i = 0; i < 2; i++) {
            const int b = b0g + i;
            const float* xprow = XP + ((size_t)b * TD + t) * G3 + jg0;
            const float2 xz2 = *(const float2*)(xprow);
            const float2 xr2 = *(const float2*)(xprow + HD);
            const float2 xh2 = *(const float2*)(xprow + 2 * HD);
            const float2 rz2 = unpack2(az[i]);
            const float2 rr2 = unpack2(ar2[i]);
            const float2 rh2 = unpack2(ah[i]);
            const float z0 = fast_sigmoid(xz2.x + rz2.x + brz2.x);
            const float z1 = fast_sigmoid(xz2.y + rz2.y + brz2.y);
            const float r0 = fast_sigmoid(xr2.x + rr2.x + brr2.x);
            const float r1 = fast_sigmoid(xr2.y + rr2.y + brr2.y);
            const float hh0 = fast_tanh(xh2.x + r0 * (rh2.x + brh2.x));
            const float hh1 = fast_tanh(xh2.y + r1 * (rh2.y + brh2.y));
            const float ho0 = hs[(size_t)(jg0 + 0) * 64 + bloc + i];
            const float ho1 = hs[(size_t)(jg0 + 1) * 64 + bloc + i];
            hn[i].x = z0 * ho0 + (1.0f - z0) * hh0;
            hn[i].y = z1 * ho1 + (1.0f - z1) * hh1;
            *(float2*)(seq + ((size_t)b * TD + t) * HD + jg0) = hn[i];
        }
        *(float2*)(hnxt + (size_t)(jg0 + 0) * BD + b0g) = make_float2(hn[0].x, hn[1].x);
        *(float2*)(hnxt + (size_t)(jg0 + 1) * BD + b0g) = make_float2(hn[0].y, hn[1].y);

        // grid barrier
        bar_target += gridDim.x;
        __syncthreads();
        if (tid == 0) {
            __threadfence();
            atomicAdd(bar, 1u);
            while (atomicAdd(bar, 0u) < bar_target) { }
            __threadfence();
        }
        __syncthreads();
    }
}

// ---------------- launch ---------------------------------------------------
extern "C" void kernel_launch(void* const* d_in, const int* in_sizes, int n_in,
                              void* d_out, int out_size) {
    const float* x      = (const float*)d_in[0];  // [128,256,512]
    const float* kern   = (const float*)d_in[1];  // [3,512,1536]
    const float* rkern  = (const float*)d_in[2];  // [3,512,1536]
    const float* biases = (const float*)d_in[3];  // [3,2,1536]
    float* out = (float*)d_out;

    cudaFuncSetAttribute(k_scan, cudaFuncAttributeMaxDynamicSharedMemorySize, SCAN_SMEM);
    cudaFuncSetAttribute(k_gemm, cudaFuncAttributeMaxDynamicSharedMemorySize, GEMM_SMEM);

    float *XP, *X1, *X2, *WuT, *hT;
    unsigned int* bar;
    cudaGetSymbolAddress((void**)&XP,  g_XP);
    cudaGetSymbolAddress((void**)&X1,  g_X1);
    cudaGetSymbolAddress((void**)&X2,  g_X2);
    cudaGetSymbolAddress((void**)&WuT, g_WuT);
    cudaGetSymbolAddress((void**)&hT,  g_hT);
    cudaGetSymbolAddress((void**)&bar, g_bar);
    float* hT0 = hT;
    float* hT1 = hT + HD * BD;

    k_trans<<<dim3(G3 / 32, HD / 32, LD), dim3(32, 8)>>>(rkern, WuT);   // 0
    k_zeroH<<<(HD * BD + 255) / 256, 256>>>(hT0, HD * BD);              // 1
    k_zeroBar<<<1, 32>>>();                                             // 2

    const float* cur = x;
    float* outs[3] = {X1, X2, out};
    for (int l = 0; l < LD; l++) {
        const float* Wk = kern + (size_t)l * HD * G3;
        const float* b0 = biases + (size_t)l * 2 * G3;
        k_gemm<<<dim3(G3 / 128, MD / 128), 256, GEMM_SMEM>>>(cur, Wk, b0, XP);
        k_scan<<<128, SCAN_THREADS, SCAN_SMEM>>>(
            XP, WuT + (size_t)l * G3 * HD, b0 + G3, outs[l], hT0, hT1, bar + l);
        cur = outs[l];
    }
    k_final<<<(HD * BD + 511) / 512, 512>>>(hT0, out + (size_t)MD * HD);
}